// round 9
// baseline (speedup 1.0000x reference)
#include <cuda_runtime.h>
#include <cuda_bf16.h>
#include <cstdint>

#define NUM_PINS_MAX   2000000
#define MAX_BLOCKS     4096

// Scratch: packed (x,y) per pin, per-block partials, reduction counter.
__device__ float2       g_pinxy[NUM_PINS_MAX];
__device__ double       g_partials[MAX_BLOCKS];
__device__ unsigned int g_counter = 0;

// ---------------------------------------------------------------------------
// Kernel A: pack x/y halves of pin_pos into float2, 8 pins per thread
// (4x float4 loads + 4x float4 stores -> deeper ILP than the 4-pin version).
// g_pinxy address taken in DEVICE code only (host-side __device__ symbol ref
// silently hits ATS host shadow memory on GB300).
// ---------------------------------------------------------------------------
__global__ void __launch_bounds__(256)
pack_pins_kernel(const float4* __restrict__ x4,
                 const float4* __restrict__ y4,
                 int n8)                      // n_pins / 8
{
    float4* __restrict__ out4 = reinterpret_cast<float4*>(g_pinxy);
    int i = blockIdx.x * blockDim.x + threadIdx.x;
    if (i < n8) {
        float4 xa = x4[2 * i];
        float4 xb = x4[2 * i + 1];
        float4 ya = y4[2 * i];
        float4 yb = y4[2 * i + 1];
        out4[4 * i]     = make_float4(xa.x, ya.x, xa.y, ya.y);
        out4[4 * i + 1] = make_float4(xa.z, ya.z, xa.w, ya.w);
        out4[4 * i + 2] = make_float4(xb.x, yb.x, xb.y, yb.y);
        out4[4 * i + 3] = make_float4(xb.z, yb.z, xb.w, yb.w);
    }
}

// ---------------------------------------------------------------------------
// Kernel B: main pair loop — the best-measured (R5) hot loop, unchanged:
// ONE quad per iteration (4 gathers + 2 streaming loads in flight), deep
// grid-stride loop, one resident wave. Fused last-block final reduction.
// ---------------------------------------------------------------------------
__global__ void __launch_bounds__(256, 8)
pair_attraction_kernel(const int4*   __restrict__ pairs4,   // [n_quads] (a0,b0,a1,b1)
                       const float2* __restrict__ w2,       // [n_quads]
                       int n_quads,
                       float* __restrict__ out)
{
    const float2* __restrict__ pinxy = g_pinxy;

    float acc0 = 0.0f, acc1 = 0.0f;
    int stride = gridDim.x * blockDim.x;

    for (int i = blockIdx.x * blockDim.x + threadIdx.x; i < n_quads; i += stride) {
        // streaming loads, evict-first, fully coalesced within each warp
        int4   p = __ldcs(&pairs4[i]);
        float2 w = __ldcs(&w2[i]);

        float2 a0 = __ldg(&pinxy[p.x]);
        float2 b0 = __ldg(&pinxy[p.y]);
        float2 a1 = __ldg(&pinxy[p.z]);
        float2 b1 = __ldg(&pinxy[p.w]);

        float dx0 = a0.x - b0.x, dy0 = a0.y - b0.y;
        float dx1 = a1.x - b1.x, dy1 = a1.y - b1.y;

        acc0 = fmaf(w.x, fmaf(dx0, dx0, dy0 * dy0), acc0);
        acc1 = fmaf(w.y, fmaf(dx1, dx1, dy1 * dy1), acc1);
    }

    float acc = acc0 + acc1;

    // warp reduce (fp32)
    #pragma unroll
    for (int off = 16; off > 0; off >>= 1)
        acc += __shfl_xor_sync(0xFFFFFFFFu, acc, off);

    // block reduce via shared (double for cross-warp combine)
    __shared__ double warp_sums[8];   // 256 threads = 8 warps
    int lane = threadIdx.x & 31;
    int wid  = threadIdx.x >> 5;
    if (lane == 0) warp_sums[wid] = (double)acc;
    __syncthreads();

    if (wid == 0) {
        double v = (lane < 8) ? warp_sums[lane] : 0.0;
        #pragma unroll
        for (int off = 4; off > 0; off >>= 1)
            v += __shfl_xor_sync(0xFFFFFFFFu, v, off);
        if (lane == 0) g_partials[blockIdx.x] = v;
    }

    // ---- last-block final reduction ----
    __shared__ bool is_last;
    if (threadIdx.x == 0) {
        __threadfence();  // make this block's partial visible
        unsigned int old = atomicAdd(&g_counter, 1u);
        is_last = (old == gridDim.x - 1);
    }
    __syncthreads();

    if (is_last) {
        __threadfence();  // acquire: see all other blocks' partials
        double v = 0.0;
        for (int i = threadIdx.x; i < (int)gridDim.x; i += blockDim.x)
            v += g_partials[i];

        #pragma unroll
        for (int off = 16; off > 0; off >>= 1)
            v += __shfl_xor_sync(0xFFFFFFFFu, v, off);

        __shared__ double fin[8];
        if (lane == 0) fin[wid] = v;
        __syncthreads();

        if (wid == 0) {
            double s = (lane < 8) ? fin[lane] : 0.0;
            #pragma unroll
            for (int off = 4; off > 0; off >>= 1)
                s += __shfl_xor_sync(0xFFFFFFFFu, s, off);
            if (lane == 0) {
                out[0] = (float)s;
                g_counter = 0;   // reset for next graph replay (deterministic)
            }
        }
    }
}

// ---------------------------------------------------------------------------
// Launcher: two kernels, pair grid = one full resident wave on the real SM
// count (152 on GB300).
// ---------------------------------------------------------------------------
extern "C" void kernel_launch(void* const* d_in, const int* in_sizes, int n_in,
                              void* d_out, int out_size) {
    const float* pin_pos = (const float*)d_in[0];
    const float* weights = (const float*)d_in[1];
    const int*   pairs   = (const int*)d_in[2];
    // d_in[3] = pin_mask (unused by the reference computation)

    int n_pins  = in_sizes[0] / 2;          // 2,000,000
    int n_pairs = in_sizes[2] / 2;          // 10,000,000
    int n_quads = n_pairs / 2;              // 5,000,000

    float* out = (float*)d_out;

    // A: pack pins (8 pins/thread)
    {
        int n8      = n_pins / 8;           // 250,000
        int threads = 256;
        int blocks  = (n8 + threads - 1) / threads;
        pack_pins_kernel<<<blocks, threads>>>(
            (const float4*)pin_pos,
            (const float4*)(pin_pos + n_pins),
            n8);
    }

    // B: main loop + fused final reduction — exactly one resident wave
    int threads = 256;
    int nsm = 0;
    cudaDeviceGetAttribute(&nsm, cudaDevAttrMultiProcessorCount, 0);
    if (nsm <= 0) nsm = 148;
    int blocks = nsm * 8;                   // occ 8 @ 256 threads (32 regs)
    if (blocks > MAX_BLOCKS) blocks = MAX_BLOCKS;
    pair_attraction_kernel<<<blocks, threads>>>(
        (const int4*)pairs, (const float2*)weights, n_quads, out);
}

// round 10
// speedup vs baseline: 1.0470x; 1.0470x over previous
#include <cuda_runtime.h>
#include <cuda_bf16.h>
#include <cstdint>

#define NUM_PINS_MAX   2000000
#define MAX_BLOCKS     4096

// Scratch: packed (x,y) per pin, per-block partials, reduction counter.
__device__ float2       g_pinxy[NUM_PINS_MAX];
__device__ double       g_partials[MAX_BLOCKS];
__device__ unsigned int g_counter = 0;

// ---------------------------------------------------------------------------
// Kernel A: pack x/y halves of pin_pos into float2 array, 4 pins per thread
// (best-measured pack config: 4.5us). g_pinxy address taken in DEVICE code
// only (host-side __device__ symbol ref hits ATS host shadow mem on GB300).
// ---------------------------------------------------------------------------
__global__ void __launch_bounds__(256)
pack_pins_kernel(const float4* __restrict__ x4,
                 const float4* __restrict__ y4,
                 int n4)                      // n_pins / 4
{
    float4* __restrict__ out4 = reinterpret_cast<float4*>(g_pinxy);
    int i = blockIdx.x * blockDim.x + threadIdx.x;
    if (i < n4) {
        float4 x = x4[i];
        float4 y = y4[i];
        out4[2 * i]     = make_float4(x.x, y.x, x.y, y.y);
        out4[2 * i + 1] = make_float4(x.z, y.z, x.w, y.w);
    }
}

// ---------------------------------------------------------------------------
// Kernel B: main pair loop — R5 structure (best measured), ONE quad per
// iteration. Gathers use __ldcg: L2-cached, NO L1 line allocation — the 16MB
// random pin set has ~1.4% L1 hit rate, so L1 fills are pure overhead on the
// saturated L1tex pipe. Streaming loads stay __ldcs (evict-first).
// Fused last-block final reduction.
// ---------------------------------------------------------------------------
__global__ void __launch_bounds__(256, 8)
pair_attraction_kernel(const int4*   __restrict__ pairs4,   // [n_quads] (a0,b0,a1,b1)
                       const float2* __restrict__ w2,       // [n_quads]
                       int n_quads,
                       float* __restrict__ out)
{
    const float2* __restrict__ pinxy = g_pinxy;

    float acc0 = 0.0f, acc1 = 0.0f;
    int stride = gridDim.x * blockDim.x;

    for (int i = blockIdx.x * blockDim.x + threadIdx.x; i < n_quads; i += stride) {
        // streaming loads, evict-first, fully coalesced within each warp
        int4   p = __ldcs(&pairs4[i]);
        float2 w = __ldcs(&w2[i]);

        // random gathers: L2-cached, no L1 allocate
        float2 a0 = __ldcg(&pinxy[p.x]);
        float2 b0 = __ldcg(&pinxy[p.y]);
        float2 a1 = __ldcg(&pinxy[p.z]);
        float2 b1 = __ldcg(&pinxy[p.w]);

        float dx0 = a0.x - b0.x, dy0 = a0.y - b0.y;
        float dx1 = a1.x - b1.x, dy1 = a1.y - b1.y;

        acc0 = fmaf(w.x, fmaf(dx0, dx0, dy0 * dy0), acc0);
        acc1 = fmaf(w.y, fmaf(dx1, dx1, dy1 * dy1), acc1);
    }

    float acc = acc0 + acc1;

    // warp reduce (fp32)
    #pragma unroll
    for (int off = 16; off > 0; off >>= 1)
        acc += __shfl_xor_sync(0xFFFFFFFFu, acc, off);

    // block reduce via shared (double for cross-warp combine)
    __shared__ double warp_sums[8];   // 256 threads = 8 warps
    int lane = threadIdx.x & 31;
    int wid  = threadIdx.x >> 5;
    if (lane == 0) warp_sums[wid] = (double)acc;
    __syncthreads();

    if (wid == 0) {
        double v = (lane < 8) ? warp_sums[lane] : 0.0;
        #pragma unroll
        for (int off = 4; off > 0; off >>= 1)
            v += __shfl_xor_sync(0xFFFFFFFFu, v, off);
        if (lane == 0) g_partials[blockIdx.x] = v;
    }

    // ---- last-block final reduction ----
    __shared__ bool is_last;
    if (threadIdx.x == 0) {
        __threadfence();  // make this block's partial visible
        unsigned int old = atomicAdd(&g_counter, 1u);
        is_last = (old == gridDim.x - 1);
    }
    __syncthreads();

    if (is_last) {
        __threadfence();  // acquire: see all other blocks' partials
        double v = 0.0;
        for (int i = threadIdx.x; i < (int)gridDim.x; i += blockDim.x)
            v += g_partials[i];

        #pragma unroll
        for (int off = 16; off > 0; off >>= 1)
            v += __shfl_xor_sync(0xFFFFFFFFu, v, off);

        __shared__ double fin[8];
        if (lane == 0) fin[wid] = v;
        __syncthreads();

        if (wid == 0) {
            double s = (lane < 8) ? fin[lane] : 0.0;
            #pragma unroll
            for (int off = 4; off > 0; off >>= 1)
                s += __shfl_xor_sync(0xFFFFFFFFu, s, off);
            if (lane == 0) {
                out[0] = (float)s;
                g_counter = 0;   // reset for next graph replay (deterministic)
            }
        }
    }
}

// ---------------------------------------------------------------------------
// Launcher (R5 configuration: 1184 blocks — best measured)
// ---------------------------------------------------------------------------
extern "C" void kernel_launch(void* const* d_in, const int* in_sizes, int n_in,
                              void* d_out, int out_size) {
    const float* pin_pos = (const float*)d_in[0];
    const float* weights = (const float*)d_in[1];
    const int*   pairs   = (const int*)d_in[2];
    // d_in[3] = pin_mask (unused by the reference computation)

    int n_pins  = in_sizes[0] / 2;          // 2,000,000
    int n_pairs = in_sizes[2] / 2;          // 10,000,000
    int n_quads = n_pairs / 2;              // 5,000,000

    float* out = (float*)d_out;

    // A: pack pins (vectorized, 4 pins/thread)
    {
        int n4      = n_pins / 4;           // 500,000
        int threads = 256;
        int blocks  = (n4 + threads - 1) / threads;
        pack_pins_kernel<<<blocks, threads>>>(
            (const float4*)pin_pos,
            (const float4*)(pin_pos + n_pins),
            n4);
    }

    // B: main loop + fused final reduction
    int threads = 256;
    int blocks  = 148 * 8;                  // 1184 blocks (best measured)
    if (blocks > MAX_BLOCKS) blocks = MAX_BLOCKS;
    pair_attraction_kernel<<<blocks, threads>>>(
        (const int4*)pairs, (const float2*)weights, n_quads, out);
}

// round 11
// speedup vs baseline: 1.0497x; 1.0026x over previous
#include <cuda_runtime.h>
#include <cuda_bf16.h>
#include <cstdint>

#define NUM_PINS_MAX   2000000
#define MAX_BLOCKS     4096

// Scratch: packed (x,y) per pin, per-block partials, reduction counter.
__device__ float2       g_pinxy[NUM_PINS_MAX];
__device__ double       g_partials[MAX_BLOCKS];
__device__ unsigned int g_counter = 0;

// ---------------------------------------------------------------------------
// Kernel A: pack x/y halves of pin_pos into float2 array, 4 pins per thread.
// Triggers programmatic launch completion after its stores so the PDL-chained
// pair kernel can overlap its prologue with the pack tail.
// g_pinxy address taken in DEVICE code only (host-side __device__ symbol ref
// hits ATS host shadow memory on GB300).
// ---------------------------------------------------------------------------
__global__ void __launch_bounds__(256)
pack_pins_kernel(const float4* __restrict__ x4,
                 const float4* __restrict__ y4,
                 int n4)                      // n_pins / 4
{
    float4* __restrict__ out4 = reinterpret_cast<float4*>(g_pinxy);
    int i = blockIdx.x * blockDim.x + threadIdx.x;
    if (i < n4) {
        float4 x = x4[i];
        float4 y = y4[i];
        out4[2 * i]     = make_float4(x.x, y.x, x.y, y.y);
        out4[2 * i + 1] = make_float4(x.z, y.z, x.w, y.w);
    }
    cudaTriggerProgrammaticLaunchCompletion();
}

// ---------------------------------------------------------------------------
// Kernel B: main pair loop — R10 structure (best measured), ONE quad/iter,
// __ldcg gathers (no L1 allocate), __ldcs streaming. PDL prologue: peel
// iteration 0's pack-independent streaming loads BEFORE
// cudaGridDependencySynchronize(), gathers after. Hot loop unchanged.
// Fused last-block final reduction.
// ---------------------------------------------------------------------------
__global__ void __launch_bounds__(256, 8)
pair_attraction_kernel(const int4*   __restrict__ pairs4,   // [n_quads] (a0,b0,a1,b1)
                       const float2* __restrict__ w2,       // [n_quads]
                       int n_quads,
                       float* __restrict__ out)
{
    const float2* __restrict__ pinxy = g_pinxy;

    const int tid0   = blockIdx.x * blockDim.x + threadIdx.x;
    const int stride = gridDim.x * blockDim.x;

    float acc0 = 0.0f, acc1 = 0.0f;

    // ---- PDL prologue: pack-independent work before the dependency sync ----
    int4   p0;
    float2 w0;
    const bool have0 = (tid0 < n_quads);
    if (have0) {
        p0 = __ldcs(&pairs4[tid0]);
        w0 = __ldcs(&w2[tid0]);
    }

    cudaGridDependencySynchronize();   // wait until pack's stores are visible

    if (have0) {
        float2 a0 = __ldcg(&pinxy[p0.x]);
        float2 b0 = __ldcg(&pinxy[p0.y]);
        float2 a1 = __ldcg(&pinxy[p0.z]);
        float2 b1 = __ldcg(&pinxy[p0.w]);
        float dx0 = a0.x - b0.x, dy0 = a0.y - b0.y;
        float dx1 = a1.x - b1.x, dy1 = a1.y - b1.y;
        acc0 = fmaf(w0.x, fmaf(dx0, dx0, dy0 * dy0), acc0);
        acc1 = fmaf(w0.y, fmaf(dx1, dx1, dy1 * dy1), acc1);
    }

    // ---- main loop (unchanged R10 hot loop, from iteration 1) ----
    for (int i = tid0 + stride; i < n_quads; i += stride) {
        int4   p = __ldcs(&pairs4[i]);
        float2 w = __ldcs(&w2[i]);

        float2 a0 = __ldcg(&pinxy[p.x]);
        float2 b0 = __ldcg(&pinxy[p.y]);
        float2 a1 = __ldcg(&pinxy[p.z]);
        float2 b1 = __ldcg(&pinxy[p.w]);

        float dx0 = a0.x - b0.x, dy0 = a0.y - b0.y;
        float dx1 = a1.x - b1.x, dy1 = a1.y - b1.y;

        acc0 = fmaf(w.x, fmaf(dx0, dx0, dy0 * dy0), acc0);
        acc1 = fmaf(w.y, fmaf(dx1, dx1, dy1 * dy1), acc1);
    }

    float acc = acc0 + acc1;

    // warp reduce (fp32)
    #pragma unroll
    for (int off = 16; off > 0; off >>= 1)
        acc += __shfl_xor_sync(0xFFFFFFFFu, acc, off);

    // block reduce via shared (double for cross-warp combine)
    __shared__ double warp_sums[8];   // 256 threads = 8 warps
    int lane = threadIdx.x & 31;
    int wid  = threadIdx.x >> 5;
    if (lane == 0) warp_sums[wid] = (double)acc;
    __syncthreads();

    if (wid == 0) {
        double v = (lane < 8) ? warp_sums[lane] : 0.0;
        #pragma unroll
        for (int off = 4; off > 0; off >>= 1)
            v += __shfl_xor_sync(0xFFFFFFFFu, v, off);
        if (lane == 0) g_partials[blockIdx.x] = v;
    }

    // ---- last-block final reduction ----
    __shared__ bool is_last;
    if (threadIdx.x == 0) {
        __threadfence();  // make this block's partial visible
        unsigned int old = atomicAdd(&g_counter, 1u);
        is_last = (old == gridDim.x - 1);
    }
    __syncthreads();

    if (is_last) {
        __threadfence();  // acquire: see all other blocks' partials
        double v = 0.0;
        for (int i = threadIdx.x; i < (int)gridDim.x; i += blockDim.x)
            v += g_partials[i];

        #pragma unroll
        for (int off = 16; off > 0; off >>= 1)
            v += __shfl_xor_sync(0xFFFFFFFFu, v, off);

        __shared__ double fin[8];
        if (lane == 0) fin[wid] = v;
        __syncthreads();

        if (wid == 0) {
            double s = (lane < 8) ? fin[lane] : 0.0;
            #pragma unroll
            for (int off = 4; off > 0; off >>= 1)
                s += __shfl_xor_sync(0xFFFFFFFFu, s, off);
            if (lane == 0) {
                out[0] = (float)s;
                g_counter = 0;   // reset for next graph replay (deterministic)
            }
        }
    }
}

// ---------------------------------------------------------------------------
// Launcher: pack, then pair with PROGRAMMATIC DEPENDENT LAUNCH so the pair
// kernel's prologue overlaps the pack tail + launch gap.
// ---------------------------------------------------------------------------
extern "C" void kernel_launch(void* const* d_in, const int* in_sizes, int n_in,
                              void* d_out, int out_size) {
    const float* pin_pos = (const float*)d_in[0];
    const float* weights = (const float*)d_in[1];
    const int*   pairs   = (const int*)d_in[2];
    // d_in[3] = pin_mask (unused by the reference computation)

    int n_pins  = in_sizes[0] / 2;          // 2,000,000
    int n_pairs = in_sizes[2] / 2;          // 10,000,000
    int n_quads = n_pairs / 2;              // 5,000,000

    float* out = (float*)d_out;

    // A: pack pins (vectorized, 4 pins/thread)
    {
        int n4      = n_pins / 4;           // 500,000
        int threads = 256;
        int blocks  = (n4 + threads - 1) / threads;
        pack_pins_kernel<<<blocks, threads>>>(
            (const float4*)pin_pos,
            (const float4*)(pin_pos + n_pins),
            n4);
    }

    // B: main loop + fused final reduction, PDL-chained to pack
    {
        int threads = 256;
        int blocks  = 148 * 8;              // 1184 blocks (best measured)
        if (blocks > MAX_BLOCKS) blocks = MAX_BLOCKS;

        cudaLaunchConfig_t cfg = {};
        cfg.gridDim  = dim3((unsigned)blocks, 1, 1);
        cfg.blockDim = dim3((unsigned)threads, 1, 1);
        cfg.dynamicSmemBytes = 0;
        cfg.stream = 0;   // same (capture) stream as the pack launch

        cudaLaunchAttribute attrs[1];
        attrs[0].id = cudaLaunchAttributeProgrammaticStreamSerialization;
        attrs[0].val.programmaticStreamSerializationAllowed = 1;
        cfg.attrs    = attrs;
        cfg.numAttrs = 1;

        const int4*   pairs4 = (const int4*)pairs;
        const float2* w2     = (const float2*)weights;
        cudaLaunchKernelEx(&cfg, pair_attraction_kernel,
                           pairs4, w2, n_quads, out);
    }
}